// round 6
// baseline (speedup 1.0000x reference)
#include <cuda_runtime.h>
#include <cuda_bf16.h>
#include <cstdint>

// Problem constants (fixed by dataset)
#define B_DIM   2048
#define IN_DIM  1024
#define H_DIM   2048
#define OUT_DIM 1024
#define BSB     32
#define RBX     64
#define NNZ     (64 * 32)

// ---------------------------------------------------------------------------
// Pre-split bf16 hi/lo device globals (no allocation allowed)
// ---------------------------------------------------------------------------
__device__ __nv_bfloat16 g_xhi[(size_t)B_DIM * IN_DIM],  g_xlo[(size_t)B_DIM * IN_DIM];
__device__ __nv_bfloat16 g_w1hi[(size_t)H_DIM * IN_DIM], g_w1lo[(size_t)H_DIM * IN_DIM];
__device__ __nv_bfloat16 g_w3hi[(size_t)OUT_DIM * H_DIM],g_w3lo[(size_t)OUT_DIM * H_DIM];
__device__ __nv_bfloat16 g_vhi[(size_t)NNZ * BSB * BSB], g_vlo[(size_t)NNZ * BSB * BSB];
__device__ __nv_bfloat16 g_h1hi[(size_t)B_DIM * H_DIM],  g_h1lo[(size_t)B_DIM * H_DIM];
__device__ __nv_bfloat16 g_h2hi[(size_t)B_DIM * H_DIM],  g_h2lo[(size_t)B_DIM * H_DIM];

// ---------------------------------------------------------------------------
// Helpers
// ---------------------------------------------------------------------------
__device__ __forceinline__ uint32_t smem_u32(const void* p) {
    uint32_t a;
    asm("{ .reg .u64 t; cvta.to.shared.u64 t, %1; cvt.u32.u64 %0, t; }"
        : "=r"(a) : "l"(p));
    return a;
}

__device__ __forceinline__ void cp16(uint32_t dst, const void* src) {
    asm volatile("cp.async.cg.shared.global [%0], [%1], 16;"
                 :: "r"(dst), "l"(src) : "memory");
}
#define CP_COMMIT() asm volatile("cp.async.commit_group;" ::: "memory")
#define CP_WAIT(N)  asm volatile("cp.async.wait_group %0;" :: "n"(N) : "memory")

__device__ __forceinline__ void ldsm_x4(uint32_t (&r)[4], uint32_t addr) {
    asm volatile("ldmatrix.sync.aligned.m8n8.x4.shared.b16 {%0,%1,%2,%3}, [%4];"
                 : "=r"(r[0]), "=r"(r[1]), "=r"(r[2]), "=r"(r[3]) : "r"(addr));
}

__device__ __forceinline__ void mma_bf16(float c[4], const uint32_t a[4],
                                         const uint32_t b[2]) {
    asm volatile(
        "mma.sync.aligned.m16n8k16.row.col.f32.bf16.bf16.f32 "
        "{%0,%1,%2,%3}, {%4,%5,%6,%7}, {%8,%9}, {%0,%1,%2,%3};"
        : "+f"(c[0]), "+f"(c[1]), "+f"(c[2]), "+f"(c[3])
        : "r"(a[0]), "r"(a[1]), "r"(a[2]), "r"(a[3]), "r"(b[0]), "r"(b[1]));
}

__device__ __forceinline__ void split1(float v, __nv_bfloat16& h, __nv_bfloat16& l) {
    h = __float2bfloat16_rn(v);
    l = __float2bfloat16_rn(v - __bfloat162float(h));
}

// ---------------------------------------------------------------------------
// Fused split kernel: 4 arrays, fp32 -> bf16 hi/lo (blockIdx.y selects array)
// ---------------------------------------------------------------------------
struct SplitArgs {
    const float4* src[4];
    uint2* hi[4];
    uint2* lo[4];
};

__global__ __launch_bounds__(256) void split4_kernel(SplitArgs args, int n4)
{
    const int a = blockIdx.y;
    const int i = blockIdx.x * 256 + threadIdx.x;
    if (i >= n4) return;
    float4 v = args.src[a][i];
    __nv_bfloat162 h0 = __floats2bfloat162_rn(v.x, v.y);
    __nv_bfloat162 h1 = __floats2bfloat162_rn(v.z, v.w);
    float2 f0 = __bfloat1622float2(h0);
    float2 f1 = __bfloat1622float2(h1);
    __nv_bfloat162 l0 = __floats2bfloat162_rn(v.x - f0.x, v.y - f0.y);
    __nv_bfloat162 l1 = __floats2bfloat162_rn(v.z - f1.x, v.w - f1.y);
    uint2 hw; hw.x = *(uint32_t*)&h0; hw.y = *(uint32_t*)&h1;
    uint2 lw; lw.x = *(uint32_t*)&l0; lw.y = *(uint32_t*)&l1;
    args.hi[a][i] = hw;
    args.lo[a][i] = lw;
}

// ---------------------------------------------------------------------------
// Dense GEMM (NT): C = act(A @ B^T + bias). A,B pre-split bf16 hi/lo.
// CTA 128(M) x 64(N), 8 warps (32x32 warp tiles), K-chunk 32, 2-stage cp.async.
// smem 60KB/CTA, <=128 regs -> 2 CTAs/SM.
// MODE 0: fp32 out + bias.  MODE 1: relu, write bf16 hi/lo arrays.
// ---------------------------------------------------------------------------
#define ROWB     80
#define D_AT     (128 * ROWB)                 // 10240 B per A matrix
#define D_BT     (64 * ROWB)                  // 5120 B per B matrix
#define D_BHI    (2 * D_AT)                   // 20480
#define D_BLO    (2 * D_AT + D_BT)            // 25600
#define DSTG     (2 * D_AT + 2 * D_BT)        // 30720 B per stage
#define D_SMEM   (2 * DSTG)                   // 61440 B

template <int MODE>
__global__ __launch_bounds__(256, 2) void gemm_cp_kernel(
    const __nv_bfloat16* __restrict__ Ahi, const __nv_bfloat16* __restrict__ Alo,
    const __nv_bfloat16* __restrict__ Bhi, const __nv_bfloat16* __restrict__ Blo,
    const float* __restrict__ bias, float* __restrict__ Cf,
    __nv_bfloat16* __restrict__ Chi, __nv_bfloat16* __restrict__ Clo,
    int N, int K)
{
    extern __shared__ char sm[];
    const uint32_t sb = smem_u32(sm);
    const int tid  = threadIdx.x;
    const int lane = tid & 31;
    const int wid  = tid >> 5;
    const int brow = blockIdx.y * 128;
    const int bcol = blockIdx.x * 64;
    const int wm = (wid >> 1) * 32;
    const int wn = (wid & 1) * 32;
    const int chunks = K / 32;

    float acc[2][4][4];
#pragma unroll
    for (int i = 0; i < 2; i++)
#pragma unroll
        for (int j = 0; j < 4; j++)
#pragma unroll
            for (int r = 0; r < 4; r++) acc[i][j][r] = 0.0f;

    auto issue = [&](int ki) {
        const int k0 = ki * 32;
        const uint32_t bufo = sb + (uint32_t)(ki & 1) * DSTG;
        // A: 512 segs of 16B per matrix (128 rows x 4)
#pragma unroll
        for (int t = 0; t < 2; t++) {
            const int seg = tid + t * 256;
            const int row = seg >> 2, s = seg & 3;
            const uint32_t d = bufo + row * ROWB + s * 16;
            const size_t ga = (size_t)(brow + row) * K + k0 + s * 8;
            cp16(d,        Ahi + ga);
            cp16(d + D_AT, Alo + ga);
        }
        // B: 256 segs per matrix (64 rows x 4)
        {
            const int row = tid >> 2, s = tid & 3;
            const uint32_t d = bufo + row * ROWB + s * 16;
            const size_t gb = (size_t)(bcol + row) * K + k0 + s * 8;
            cp16(d + D_BHI, Bhi + gb);
            cp16(d + D_BLO, Blo + gb);
        }
    };

    issue(0);
    CP_COMMIT();

    const uint32_t aoff = (wm + (lane & 15)) * ROWB + ((lane >> 4) & 1) * 16;
    const uint32_t boff = (wn + ((lane >> 4) & 1) * 8 + (lane & 7)) * ROWB +
                          ((lane >> 3) & 1) * 16;

    for (int kc = 0; kc < chunks; kc++) {
        if (kc + 1 < chunks) { issue(kc + 1); CP_COMMIT(); CP_WAIT(1); }
        else                 { CP_WAIT(0); }
        __syncthreads();

        const uint32_t base = sb + (uint32_t)(kc & 1) * DSTG;
#pragma unroll
        for (int ks = 0; ks < 2; ks++) {
            // Pass 1: A_hi x B_hi
            uint32_t ah[2][4];
#pragma unroll
            for (int i = 0; i < 2; i++)
                ldsm_x4(ah[i], base + aoff + i * (16 * ROWB) + ks * 32);
            uint32_t bh[2][4];
#pragma unroll
            for (int jp = 0; jp < 2; jp++)
                ldsm_x4(bh[jp], base + D_BHI + boff + jp * (16 * ROWB) + ks * 32);
#pragma unroll
            for (int i = 0; i < 2; i++)
#pragma unroll
                for (int j = 0; j < 4; j++)
                    mma_bf16(acc[i][j], ah[i], &bh[j >> 1][(j & 1) * 2]);
            // Pass 2: A_hi x B_lo
            {
                uint32_t bl[2][4];
#pragma unroll
                for (int jp = 0; jp < 2; jp++)
                    ldsm_x4(bl[jp], base + D_BLO + boff + jp * (16 * ROWB) + ks * 32);
#pragma unroll
                for (int i = 0; i < 2; i++)
#pragma unroll
                    for (int j = 0; j < 4; j++)
                        mma_bf16(acc[i][j], ah[i], &bl[j >> 1][(j & 1) * 2]);
            }
            // Pass 3: A_lo x B_hi (reuse ah regs)
#pragma unroll
            for (int i = 0; i < 2; i++)
                ldsm_x4(ah[i], base + D_AT + aoff + i * (16 * ROWB) + ks * 32);
#pragma unroll
            for (int i = 0; i < 2; i++)
#pragma unroll
                for (int j = 0; j < 4; j++)
                    mma_bf16(acc[i][j], ah[i], &bh[j >> 1][(j & 1) * 2]);
        }
        __syncthreads();
    }

    // epilogue
#pragma unroll
    for (int i = 0; i < 2; i++) {
        const int r0 = brow + wm + i * 16 + (lane >> 2);
#pragma unroll
        for (int j = 0; j < 4; j++) {
            const int c0 = bcol + wn + j * 8 + 2 * (lane & 3);
            const float bx = __ldg(&bias[c0]), by = __ldg(&bias[c0 + 1]);
            float v00 = acc[i][j][0] + bx, v01 = acc[i][j][1] + by;
            float v10 = acc[i][j][2] + bx, v11 = acc[i][j][3] + by;
            if (MODE == 0) {
                *(float2*)(Cf + (size_t)r0 * N + c0)       = make_float2(v00, v01);
                *(float2*)(Cf + (size_t)(r0 + 8) * N + c0) = make_float2(v10, v11);
            } else {
                v00 = fmaxf(v00, 0.f); v01 = fmaxf(v01, 0.f);
                v10 = fmaxf(v10, 0.f); v11 = fmaxf(v11, 0.f);
                __nv_bfloat16 h0, l0, h1, l1;
                split1(v00, h0, l0); split1(v01, h1, l1);
                *(__nv_bfloat162*)(Chi + (size_t)r0 * N + c0) = __nv_bfloat162(h0, h1);
                *(__nv_bfloat162*)(Clo + (size_t)r0 * N + c0) = __nv_bfloat162(l0, l1);
                split1(v10, h0, l0); split1(v11, h1, l1);
                *(__nv_bfloat162*)(Chi + (size_t)(r0 + 8) * N + c0) = __nv_bfloat162(h0, h1);
                *(__nv_bfloat162*)(Clo + (size_t)(r0 + 8) * N + c0) = __nv_bfloat162(l0, l1);
            }
        }
    }
}

// ---------------------------------------------------------------------------
// BSR layer: per (batch-tile 256, row-block rb):
//   h2[., rb*32:+32] = relu( sum_p h1[., col_p*32:+32] @ vals[p]^T + b2 )
// CTA 256(batch) x 32(N), 8 warps (32x32 warp tiles), 2-stage cp.async.
// smem 90KB/CTA -> 2 CTAs/SM.
// ---------------------------------------------------------------------------
#define S_AT     (256 * ROWB)                 // 20480 B per A matrix
#define S_BT     (32 * ROWB)                  // 2560 B per B matrix
#define S_BHI    (2 * S_AT)                   // 40960
#define S_BLO    (2 * S_AT + S_BT)            // 43520
#define SSTG     (2 * S_AT + 2 * S_BT)        // 46080 B per stage
#define S_SMEM   (2 * SSTG)                   // 92160 B

__global__ __launch_bounds__(256, 2) void bsr_cp_kernel(
    const __nv_bfloat16* __restrict__ h1hi, const __nv_bfloat16* __restrict__ h1lo,
    const int* __restrict__ crow, const int* __restrict__ cols,
    const __nv_bfloat16* __restrict__ vhi, const __nv_bfloat16* __restrict__ vlo,
    const float* __restrict__ bias,
    __nv_bfloat16* __restrict__ h2hi, __nv_bfloat16* __restrict__ h2lo)
{
    extern __shared__ char sm[];
    const uint32_t sb = smem_u32(sm);
    const int tid  = threadIdx.x;
    const int lane = tid & 31;
    const int wid  = tid >> 5;
    const int b0 = blockIdx.x * 256;
    const int rb = blockIdx.y;
    const int wm = wid * 32;   // 8 warps x 32 batch rows

    float acc[2][4][4];
#pragma unroll
    for (int i = 0; i < 2; i++)
#pragma unroll
        for (int j = 0; j < 4; j++)
#pragma unroll
            for (int r = 0; r < 4; r++) acc[i][j][r] = 0.0f;

    const int s0 = __ldg(&crow[rb]);
    const int chunks = __ldg(&crow[rb + 1]) - s0;

    auto issue = [&](int ki) {
        const int p = s0 + ki;
        const int cb = __ldg(&cols[p]);
        const uint32_t bufo = sb + (uint32_t)(ki & 1) * SSTG;
        // A: 1024 segs per matrix (256 rows x 4)
#pragma unroll
        for (int t = 0; t < 4; t++) {
            const int seg = tid + t * 256;
            const int row = seg >> 2, s = seg & 3;
            const uint32_t d = bufo + row * ROWB + s * 16;
            const size_t ga = (size_t)(b0 + row) * H_DIM + cb * 32 + s * 8;
            cp16(d,        h1hi + ga);
            cp16(d + S_AT, h1lo + ga);
        }
        // B: 128 segs per matrix (32 rows x 4); tid<128 -> hi, else lo
        {
            const int seg = tid & 127;
            const int row = seg >> 2, s = seg & 3;
            const uint32_t d = bufo + (tid < 128 ? S_BHI : S_BLO) + row * ROWB + s * 16;
            const __nv_bfloat16* src = (tid < 128 ? vhi : vlo) +
                                       (size_t)p * (BSB * BSB) + row * BSB + s * 8;
            cp16(d, src);
        }
    };

    issue(0);
    CP_COMMIT();

    const uint32_t aoff = (wm + (lane & 15)) * ROWB + ((lane >> 4) & 1) * 16;
    const uint32_t boff = (((lane >> 4) & 1) * 8 + (lane & 7)) * ROWB +
                          ((lane >> 3) & 1) * 16;

    for (int kc = 0; kc < chunks; kc++) {
        if (kc + 1 < chunks) { issue(kc + 1); CP_COMMIT(); CP_WAIT(1); }
        else                 { CP_WAIT(0); }
        __syncthreads();

        const uint32_t base = sb + (uint32_t)(kc & 1) * SSTG;
#pragma unroll
        for (int ks = 0; ks < 2; ks++) {
            // Pass 1: A_hi x B_hi
            uint32_t ah[2][4];
#pragma unroll
            for (int i = 0; i < 2; i++)
                ldsm_x4(ah[i], base + aoff + i * (16 * ROWB) + ks * 32);
            uint32_t bh[2][4];
#pragma unroll
            for (int jp = 0; jp < 2; jp++)
                ldsm_x4(bh[jp], base + S_BHI + boff + jp * (16 * ROWB) + ks * 32);
#pragma unroll
            for (int i = 0; i < 2; i++)
#pragma unroll
                for (int j = 0; j < 4; j++)
                    mma_bf16(acc[i][j], ah[i], &bh[j >> 1][(j & 1) * 2]);
            // Pass 2: A_hi x B_lo
            {
                uint32_t bl[2][4];
#pragma unroll
                for (int jp = 0; jp < 2; jp++)
                    ldsm_x4(bl[jp], base + S_BLO + boff + jp * (16 * ROWB) + ks * 32);
#pragma unroll
                for (int i = 0; i < 2; i++)
#pragma unroll
                    for (int j = 0; j < 4; j++)
                        mma_bf16(acc[i][j], ah[i], &bl[j >> 1][(j & 1) * 2]);
            }
            // Pass 3: A_lo x B_hi
#pragma unroll
            for (int i = 0; i < 2; i++)
                ldsm_x4(ah[i], base + S_AT + aoff + i * (16 * ROWB) + ks * 32);
#pragma unroll
            for (int i = 0; i < 2; i++)
#pragma unroll
                for (int j = 0; j < 4; j++)
                    mma_bf16(acc[i][j], ah[i], &bh[j >> 1][(j & 1) * 2]);
        }
        __syncthreads();
    }

    // epilogue: bias + relu -> bf16 hi/lo
#pragma unroll
    for (int i = 0; i < 2; i++) {
        const int r0 = b0 + wm + i * 16 + (lane >> 2);
#pragma unroll
        for (int j = 0; j < 4; j++) {
            const int c0 = rb * 32 + j * 8 + 2 * (lane & 3);
            const float bx = __ldg(&bias[c0]), by = __ldg(&bias[c0 + 1]);
            float v00 = fmaxf(acc[i][j][0] + bx, 0.f);
            float v01 = fmaxf(acc[i][j][1] + by, 0.f);
            float v10 = fmaxf(acc[i][j][2] + bx, 0.f);
            float v11 = fmaxf(acc[i][j][3] + by, 0.f);
            __nv_bfloat16 h0, l0, h1, l1;
            split1(v00, h0, l0); split1(v01, h1, l1);
            *(__nv_bfloat162*)(h2hi + (size_t)r0 * H_DIM + c0) = __nv_bfloat162(h0, h1);
            *(__nv_bfloat162*)(h2lo + (size_t)r0 * H_DIM + c0) = __nv_bfloat162(l0, l1);
            split1(v10, h0, l0); split1(v11, h1, l1);
            *(__nv_bfloat162*)(h2hi + (size_t)(r0 + 8) * H_DIM + c0) = __nv_bfloat162(h0, h1);
            *(__nv_bfloat162*)(h2lo + (size_t)(r0 + 8) * H_DIM + c0) = __nv_bfloat162(l0, l1);
        }
    }
}

// ---------------------------------------------------------------------------
// Launcher
// ---------------------------------------------------------------------------
extern "C" void kernel_launch(void* const* d_in, const int* in_sizes, int n_in,
                              void* d_out, int out_size)
{
    const float* x    = (const float*)d_in[0];
    const float* W1   = (const float*)d_in[1];
    const float* b1   = (const float*)d_in[2];
    const int*   crow = (const int*)d_in[3];
    const int*   cols = (const int*)d_in[4];
    const float* vals = (const float*)d_in[5];
    const float* b2   = (const float*)d_in[6];
    const float* W3   = (const float*)d_in[7];
    const float* b3   = (const float*)d_in[8];
    float* out = (float*)d_out;

    __nv_bfloat16 *xhi, *xlo, *w1hi, *w1lo, *w3hi, *w3lo, *vhi, *vlo;
    __nv_bfloat16 *h1hi, *h1lo, *h2hi, *h2lo;
    cudaGetSymbolAddress((void**)&xhi,  g_xhi);  cudaGetSymbolAddress((void**)&xlo,  g_xlo);
    cudaGetSymbolAddress((void**)&w1hi, g_w1hi); cudaGetSymbolAddress((void**)&w1lo, g_w1lo);
    cudaGetSymbolAddress((void**)&w3hi, g_w3hi); cudaGetSymbolAddress((void**)&w3lo, g_w3lo);
    cudaGetSymbolAddress((void**)&vhi,  g_vhi);  cudaGetSymbolAddress((void**)&vlo,  g_vlo);
    cudaGetSymbolAddress((void**)&h1hi, g_h1hi); cudaGetSymbolAddress((void**)&h1lo, g_h1lo);
    cudaGetSymbolAddress((void**)&h2hi, g_h2hi); cudaGetSymbolAddress((void**)&h2lo, g_h2lo);

    cudaFuncSetAttribute(gemm_cp_kernel<0>,
                         cudaFuncAttributeMaxDynamicSharedMemorySize, D_SMEM);
    cudaFuncSetAttribute(gemm_cp_kernel<1>,
                         cudaFuncAttributeMaxDynamicSharedMemorySize, D_SMEM);
    cudaFuncSetAttribute(bsr_cp_kernel,
                         cudaFuncAttributeMaxDynamicSharedMemorySize, S_SMEM);

    // Fused pre-split of the 4 fp32 inputs (each 2M elements = 512K float4)
    const int n4 = (B_DIM * IN_DIM) / 4;
    SplitArgs sa;
    sa.src[0] = (const float4*)x;    sa.hi[0] = (uint2*)xhi;  sa.lo[0] = (uint2*)xlo;
    sa.src[1] = (const float4*)W1;   sa.hi[1] = (uint2*)w1hi; sa.lo[1] = (uint2*)w1lo;
    sa.src[2] = (const float4*)W3;   sa.hi[2] = (uint2*)w3hi; sa.lo[2] = (uint2*)w3lo;
    sa.src[3] = (const float4*)vals; sa.hi[3] = (uint2*)vhi;  sa.lo[3] = (uint2*)vlo;
    split4_kernel<<<dim3(n4 / 256, 4), 256>>>(sa, n4);

    // Layer 1: h1 = relu(x @ W1^T + b1) -> bf16 hi/lo  [grid 32x16 = 512]
    gemm_cp_kernel<1><<<dim3(H_DIM / 64, B_DIM / 128), 256, D_SMEM>>>(
        xhi, xlo, w1hi, w1lo, b1, nullptr, h1hi, h1lo, H_DIM, IN_DIM);

    // Layer 2: h2 = relu(BSR(h1) + b2) -> bf16 hi/lo   [grid 8x64 = 512]
    bsr_cp_kernel<<<dim3(B_DIM / 256, RBX), 256, S_SMEM>>>(
        h1hi, h1lo, crow, cols, vhi, vlo, b2, h2hi, h2lo);

    // Layer 3: out = h2 @ W3^T + b3 (fp32)             [grid 16x16 = 256]
    gemm_cp_kernel<0><<<dim3(OUT_DIM / 64, B_DIM / 128), 256, D_SMEM>>>(
        h2hi, h2lo, w3hi, w3lo, b3, out, nullptr, nullptr, OUT_DIM, H_DIM);
}

// round 7
// speedup vs baseline: 1.3640x; 1.3640x over previous
#include <cuda_runtime.h>
#include <cuda_fp16.h>
#include <cstdint>

// Problem constants (fixed by dataset)
#define B_DIM   2048
#define IN_DIM  1024
#define H_DIM   2048
#define OUT_DIM 1024
#define BSB     32
#define RBX     64
#define NNZ     (64 * 32)

// ---------------------------------------------------------------------------
// Device globals (no allocation allowed). fp16 everywhere.
// x / h1 / h2: split hi+lo (exact to 2^-22). W1 / W3 / vals: plain fp16.
// ---------------------------------------------------------------------------
__device__ __half g_xhi[(size_t)B_DIM * IN_DIM],  g_xlo[(size_t)B_DIM * IN_DIM];
__device__ __half g_w1[(size_t)H_DIM * IN_DIM];
__device__ __half g_w3[(size_t)OUT_DIM * H_DIM];
__device__ __half g_vals[(size_t)NNZ * BSB * BSB];
__device__ __half g_h1hi[(size_t)B_DIM * H_DIM], g_h1lo[(size_t)B_DIM * H_DIM];
__device__ __half g_h2hi[(size_t)B_DIM * H_DIM], g_h2lo[(size_t)B_DIM * H_DIM];

// ---------------------------------------------------------------------------
// Helpers
// ---------------------------------------------------------------------------
__device__ __forceinline__ uint32_t smem_u32(const void* p) {
    uint32_t a;
    asm("{ .reg .u64 t; cvta.to.shared.u64 t, %1; cvt.u32.u64 %0, t; }"
        : "=r"(a) : "l"(p));
    return a;
}

__device__ __forceinline__ void cp16(uint32_t dst, const void* src) {
    asm volatile("cp.async.cg.shared.global [%0], [%1], 16;"
                 :: "r"(dst), "l"(src) : "memory");
}
#define CP_COMMIT() asm volatile("cp.async.commit_group;" ::: "memory")
#define CP_WAIT(N)  asm volatile("cp.async.wait_group %0;" :: "n"(N) : "memory")

__device__ __forceinline__ void ldsm_x4(uint32_t (&r)[4], uint32_t addr) {
    asm volatile("ldmatrix.sync.aligned.m8n8.x4.shared.b16 {%0,%1,%2,%3}, [%4];"
                 : "=r"(r[0]), "=r"(r[1]), "=r"(r[2]), "=r"(r[3]) : "r"(addr));
}

__device__ __forceinline__ void mma_fp16(float c[4], const uint32_t a[4],
                                         const uint32_t b[2]) {
    asm volatile(
        "mma.sync.aligned.m16n8k16.row.col.f32.f16.f16.f32 "
        "{%0,%1,%2,%3}, {%4,%5,%6,%7}, {%8,%9}, {%0,%1,%2,%3};"
        : "+f"(c[0]), "+f"(c[1]), "+f"(c[2]), "+f"(c[3])
        : "r"(a[0]), "r"(a[1]), "r"(a[2]), "r"(a[3]), "r"(b[0]), "r"(b[1]));
}

__device__ __forceinline__ void split1h(float v, __half& h, __half& l) {
    h = __float2half_rn(v);
    l = __float2half_rn(v - __half2float(h));
}

// ---------------------------------------------------------------------------
// Prep kernel: blockIdx.y==0 -> split x into fp16 hi/lo;
//              blockIdx.y==1..3 -> convert W1 / W3 / vals to plain fp16.
// ---------------------------------------------------------------------------
struct PrepArgs {
    const float4* x;   uint2* xhi; uint2* xlo;
    const float4* w[3]; uint2* wf[3];
};

__global__ __launch_bounds__(256) void prep_kernel(PrepArgs args, int n4)
{
    const int a = blockIdx.y;
    const int i = blockIdx.x * 256 + threadIdx.x;
    if (i >= n4) return;
    if (a == 0) {
        float4 v = args.x[i];
        __half hx, lx, hy, ly, hz, lz, hw, lw;
        split1h(v.x, hx, lx); split1h(v.y, hy, ly);
        split1h(v.z, hz, lz); split1h(v.w, hw, lw);
        __half2 h0(hx, hy), h1(hz, hw), l0(lx, ly), l1(lz, lw);
        uint2 hu; hu.x = *(uint32_t*)&h0; hu.y = *(uint32_t*)&h1;
        uint2 lu; lu.x = *(uint32_t*)&l0; lu.y = *(uint32_t*)&l1;
        args.xhi[i] = hu;
        args.xlo[i] = lu;
    } else {
        float4 v = args.w[a - 1][i];
        __half2 h0 = __floats2half2_rn(v.x, v.y);
        __half2 h1 = __floats2half2_rn(v.z, v.w);
        uint2 hu; hu.x = *(uint32_t*)&h0; hu.y = *(uint32_t*)&h1;
        args.wf[a - 1][i] = hu;
    }
}

// ---------------------------------------------------------------------------
// Dense GEMM (NT): C = act(A @ B^T + bias).
// A split fp16 hi/lo (exact), B plain fp16 (2-pass scheme).
// CTA 128x128, 4 warps, warp tile 64x64, K-chunk 32, 2-stage cp.async.
// smem 60KB -> 2 CTAs/SM.
// MODE 0: fp32 out + bias.  MODE 1: relu, write fp16 hi/lo arrays.
// ---------------------------------------------------------------------------
#define ROWB   80                    // 64B data + 16B pad
#define D_AT   (128 * ROWB)          // 10240 B per matrix
#define DSTG   (3 * D_AT)            // Ahi, Alo, B -> 30720 B per stage
#define D_SMEM (2 * DSTG)            // 61440 B

template <int MODE>
__global__ __launch_bounds__(128, 2) void gemm_fp16_kernel(
    const __half* __restrict__ Ahi, const __half* __restrict__ Alo,
    const __half* __restrict__ Bm,
    const float* __restrict__ bias, float* __restrict__ Cf,
    __half* __restrict__ Chi, __half* __restrict__ Clo,
    int N, int K)
{
    extern __shared__ char sm[];
    const uint32_t sb = smem_u32(sm);
    const int tid  = threadIdx.x;
    const int lane = tid & 31;
    const int wid  = tid >> 5;
    const int brow = blockIdx.y * 128;
    const int bcol = blockIdx.x * 128;
    const int wm = (wid >> 1) * 64;
    const int wn = (wid & 1) * 64;
    const int chunks = K / 32;

    float acc[4][8][4];
#pragma unroll
    for (int i = 0; i < 4; i++)
#pragma unroll
        for (int j = 0; j < 8; j++)
#pragma unroll
            for (int r = 0; r < 4; r++) acc[i][j][r] = 0.0f;

    // cp.async: each matrix tile is 128 rows x 64B = 512 segs of 16B.
    auto issue = [&](int ki) {
        const int k0 = ki * 32;
        const uint32_t bufo = sb + (uint32_t)(ki & 1) * DSTG;
#pragma unroll
        for (int t = 0; t < 4; t++) {
            const int seg = tid + t * 128;
            const int row = seg >> 2, s = seg & 3;
            const uint32_t d = bufo + row * ROWB + s * 16;
            const size_t ga = (size_t)(brow + row) * K + k0 + s * 8;
            cp16(d,            Ahi + ga);
            cp16(d + D_AT,     Alo + ga);
            const size_t gb = (size_t)(bcol + row) * K + k0 + s * 8;
            cp16(d + 2 * D_AT, Bm + gb);
        }
    };

    issue(0);
    CP_COMMIT();

    const uint32_t aoff = (wm + (lane & 15)) * ROWB + ((lane >> 4) & 1) * 16;
    const uint32_t boff = (wn + ((lane >> 4) & 1) * 8 + (lane & 7)) * ROWB +
                          ((lane >> 3) & 1) * 16;

    for (int kc = 0; kc < chunks; kc++) {
        if (kc + 1 < chunks) { issue(kc + 1); CP_COMMIT(); CP_WAIT(1); }
        else                 { CP_WAIT(0); }
        __syncthreads();

        const uint32_t base = sb + (uint32_t)(kc & 1) * DSTG;
#pragma unroll
        for (int ks = 0; ks < 2; ks++) {
            // B fragments (reused across both passes)
            uint32_t bq[4][4];
#pragma unroll
            for (int jp = 0; jp < 4; jp++)
                ldsm_x4(bq[jp], base + 2 * D_AT + boff + jp * (16 * ROWB) + ks * 32);
            // Pass 1: A_hi x B
            uint32_t af[4][4];
#pragma unroll
            for (int i = 0; i < 4; i++)
                ldsm_x4(af[i], base + aoff + i * (16 * ROWB) + ks * 32);
#pragma unroll
            for (int i = 0; i < 4; i++)
#pragma unroll
                for (int j = 0; j < 8; j++)
                    mma_fp16(acc[i][j], af[i], &bq[j >> 1][(j & 1) * 2]);
            // Pass 2: A_lo x B (reuse af regs)
#pragma unroll
            for (int i = 0; i < 4; i++)
                ldsm_x4(af[i], base + D_AT + aoff + i * (16 * ROWB) + ks * 32);
#pragma unroll
            for (int i = 0; i < 4; i++)
#pragma unroll
                for (int j = 0; j < 8; j++)
                    mma_fp16(acc[i][j], af[i], &bq[j >> 1][(j & 1) * 2]);
        }
        __syncthreads();
    }

    // epilogue
#pragma unroll
    for (int i = 0; i < 4; i++) {
        const int r0 = brow + wm + i * 16 + (lane >> 2);
#pragma unroll
        for (int j = 0; j < 8; j++) {
            const int c0 = bcol + wn + j * 8 + 2 * (lane & 3);
            const float bx = __ldg(&bias[c0]), by = __ldg(&bias[c0 + 1]);
            float v00 = acc[i][j][0] + bx, v01 = acc[i][j][1] + by;
            float v10 = acc[i][j][2] + bx, v11 = acc[i][j][3] + by;
            if (MODE == 0) {
                *(float2*)(Cf + (size_t)r0 * N + c0)       = make_float2(v00, v01);
                *(float2*)(Cf + (size_t)(r0 + 8) * N + c0) = make_float2(v10, v11);
            } else {
                v00 = fmaxf(v00, 0.f); v01 = fmaxf(v01, 0.f);
                v10 = fmaxf(v10, 0.f); v11 = fmaxf(v11, 0.f);
                __half h0, l0, h1, l1;
                split1h(v00, h0, l0); split1h(v01, h1, l1);
                *(__half2*)(Chi + (size_t)r0 * N + c0) = __half2(h0, h1);
                *(__half2*)(Clo + (size_t)r0 * N + c0) = __half2(l0, l1);
                split1h(v10, h0, l0); split1h(v11, h1, l1);
                *(__half2*)(Chi + (size_t)(r0 + 8) * N + c0) = __half2(h0, h1);
                *(__half2*)(Clo + (size_t)(r0 + 8) * N + c0) = __half2(l0, l1);
            }
        }
    }
}

// ---------------------------------------------------------------------------
// BSR layer: per (batch-tile 256, row-block rb):
//   h2[., rb*32:+32] = relu( sum_p h1[., col_p*32:+32] @ vals[p]^T + b2 )
// A = h1 split hi/lo (gathered), B = vals plain fp16.
// 8 warps (32x32 warp tiles), 2-stage cp.async. smem 85KB -> 2 CTAs/SM.
// ---------------------------------------------------------------------------
#define S_AT   (256 * ROWB)                 // 20480 B per A matrix
#define S_BT   (32 * ROWB)                  // 2560 B
#define SSTG   (2 * S_AT + S_BT)            // 43520 B per stage
#define S_SMEM (2 * SSTG)                   // 87040 B

__global__ __launch_bounds__(256, 2) void bsr_fp16_kernel(
    const __half* __restrict__ h1hi, const __half* __restrict__ h1lo,
    const int* __restrict__ crow, const int* __restrict__ cols,
    const __half* __restrict__ vals,
    const float* __restrict__ bias,
    __half* __restrict__ h2hi, __half* __restrict__ h2lo)
{
    extern __shared__ char sm[];
    const uint32_t sb = smem_u32(sm);
    const int tid  = threadIdx.x;
    const int lane = tid & 31;
    const int wid  = tid >> 5;
    const int b0 = blockIdx.x * 256;
    const int rb = blockIdx.y;
    const int wm = wid * 32;

    float acc[2][4][4];
#pragma unroll
    for (int i = 0; i < 2; i++)
#pragma unroll
        for (int j = 0; j < 4; j++)
#pragma unroll
            for (int r = 0; r < 4; r++) acc[i][j][r] = 0.0f;

    const int s0 = __ldg(&crow[rb]);
    const int chunks = __ldg(&crow[rb + 1]) - s0;

    auto issue = [&](int ki) {
        const int p = s0 + ki;
        const int cb = __ldg(&cols[p]);
        const uint32_t bufo = sb + (uint32_t)(ki & 1) * SSTG;
        // A: 256 rows x 4 segs = 1024 segs per matrix
#pragma unroll
        for (int t = 0; t < 4; t++) {
            const int seg = tid + t * 256;
            const int row = seg >> 2, s = seg & 3;
            const uint32_t d = bufo + row * ROWB + s * 16;
            const size_t ga = (size_t)(b0 + row) * H_DIM + cb * 32 + s * 8;
            cp16(d,        h1hi + ga);
            cp16(d + S_AT, h1lo + ga);
        }
        // B: 32 rows x 4 segs = 128 segs
        if (tid < 128) {
            const int row = tid >> 2, s = tid & 3;
            cp16(bufo + 2 * S_AT + row * ROWB + s * 16,
                 vals + (size_t)p * (BSB * BSB) + row * BSB + s * 8);
        }
    };

    issue(0);
    CP_COMMIT();

    const uint32_t aoff = (wm + (lane & 15)) * ROWB + ((lane >> 4) & 1) * 16;
    const uint32_t boff = (((lane >> 4) & 1) * 8 + (lane & 7)) * ROWB +
                          ((lane >> 3) & 1) * 16;

    for (int kc = 0; kc < chunks; kc++) {
        if (kc + 1 < chunks) { issue(kc + 1); CP_COMMIT(); CP_WAIT(1); }
        else                 { CP_WAIT(0); }
        __syncthreads();

        const uint32_t base = sb + (uint32_t)(kc & 1) * SSTG;
#pragma unroll
        for (int ks = 0; ks < 2; ks++) {
            uint32_t bq[2][4];
#pragma unroll
            for (int jp = 0; jp < 2; jp++)
                ldsm_x4(bq[jp], base + 2 * S_AT + boff + jp * (16 * ROWB) + ks * 32);
            uint32_t af[2][4];
#pragma unroll
            for (int i = 0; i < 2; i++)
                ldsm_x4(af[i], base + aoff + i * (16 * ROWB) + ks * 32);
#pragma unroll
            for (int i = 0; i < 2; i++)
#pragma unroll
                for (int j = 0; j < 4; j++)
                    mma_fp16(acc[i][j], af[i], &bq[j >> 1][(j & 1) * 2]);
#pragma unroll
            for (int i = 0; i < 2; i++)
                ldsm_x4(af[i], base + S_AT + aoff + i * (16 * ROWB) + ks * 32);
#pragma unroll
            for (int i = 0; i < 2; i++)
#pragma unroll
                for (int j = 0; j < 4; j++)
                    mma_fp16(acc[i][j], af[i], &bq[j >> 1][(j & 1) * 2]);
        }
        __syncthreads();
    }

    // epilogue: bias + relu -> fp16 hi/lo
#pragma unroll
    for (int i = 0; i < 2; i++) {
        const int r0 = b0 + wm + i * 16 + (lane >> 2);
#pragma unroll
        for (int j = 0; j < 4; j++) {
            const int c0 = rb * 32 + j * 8 + 2 * (lane & 3);
            const float bx = __ldg(&bias[c0]), by = __ldg(&bias[c0 + 1]);
            float v00 = fmaxf(acc[i][j][0] + bx, 0.f);
            float v01 = fmaxf(acc[i][j][1] + by, 0.f);
            float v10 = fmaxf(acc[i][j][2] + bx, 0.f);
            float v11 = fmaxf(acc[i][j][3] + by, 0.f);
            __half h0, l0, h1, l1;
            split1h(v00, h0, l0); split1h(v01, h1, l1);
            *(__half2*)(h2hi + (size_t)r0 * H_DIM + c0) = __half2(h0, h1);
            *(__half2*)(h2lo + (size_t)r0 * H_DIM + c0) = __half2(l0, l1);
            split1h(v10, h0, l0); split1h(v11, h1, l1);
            *(__half2*)(h2hi + (size_t)(r0 + 8) * H_DIM + c0) = __half2(h0, h1);
            *(__half2*)(h2lo + (size_t)(r0 + 8) * H_DIM + c0) = __half2(l0, l1);
        }
    }
}

// ---------------------------------------------------------------------------
// Launcher
// ---------------------------------------------------------------------------
extern "C" void kernel_launch(void* const* d_in, const int* in_sizes, int n_in,
                              void* d_out, int out_size)
{
    const float* x    = (const float*)d_in[0];
    const float* W1   = (const float*)d_in[1];
    const float* b1   = (const float*)d_in[2];
    const int*   crow = (const int*)d_in[3];
    const int*   cols = (const int*)d_in[4];
    const float* vals = (const float*)d_in[5];
    const float* b2   = (const float*)d_in[6];
    const float* W3   = (const float*)d_in[7];
    const float* b3   = (const float*)d_in[8];
    float* out = (float*)d_out;

    __half *xhi, *xlo, *w1, *w3, *vf, *h1hi, *h1lo, *h2hi, *h2lo;
    cudaGetSymbolAddress((void**)&xhi,  g_xhi);
    cudaGetSymbolAddress((void**)&xlo,  g_xlo);
    cudaGetSymbolAddress((void**)&w1,   g_w1);
    cudaGetSymbolAddress((void**)&w3,   g_w3);
    cudaGetSymbolAddress((void**)&vf,   g_vals);
    cudaGetSymbolAddress((void**)&h1hi, g_h1hi);
    cudaGetSymbolAddress((void**)&h1lo, g_h1lo);
    cudaGetSymbolAddress((void**)&h2hi, g_h2hi);
    cudaGetSymbolAddress((void**)&h2lo, g_h2lo);

    cudaFuncSetAttribute(gemm_fp16_kernel<0>,
                         cudaFuncAttributeMaxDynamicSharedMemorySize, D_SMEM);
    cudaFuncSetAttribute(gemm_fp16_kernel<1>,
                         cudaFuncAttributeMaxDynamicSharedMemorySize, D_SMEM);
    cudaFuncSetAttribute(bsr_fp16_kernel,
                         cudaFuncAttributeMaxDynamicSharedMemorySize, S_SMEM);

    // Prep: split x to fp16 hi/lo; convert W1/W3/vals to fp16.
    const int n4 = (B_DIM * IN_DIM) / 4;   // 512K float4 per array (all 2M elems)
    PrepArgs pa;
    pa.x = (const float4*)x;  pa.xhi = (uint2*)xhi;  pa.xlo = (uint2*)xlo;
    pa.w[0] = (const float4*)W1;   pa.wf[0] = (uint2*)w1;
    pa.w[1] = (const float4*)W3;   pa.wf[1] = (uint2*)w3;
    pa.w[2] = (const float4*)vals; pa.wf[2] = (uint2*)vf;
    prep_kernel<<<dim3(n4 / 256, 4), 256>>>(pa, n4);

    // Layer 1: h1 = relu(x @ W1^T + b1) -> fp16 hi/lo   [grid 16x16]
    gemm_fp16_kernel<1><<<dim3(H_DIM / 128, B_DIM / 128), 128, D_SMEM>>>(
        xhi, xlo, w1, b1, nullptr, h1hi, h1lo, H_DIM, IN_DIM);

    // Layer 2: h2 = relu(BSR(h1) + b2) -> fp16 hi/lo    [grid 8x64]
    bsr_fp16_kernel<<<dim3(B_DIM / 256, RBX), 256, S_SMEM>>>(
        h1hi, h1lo, crow, cols, vf, b2, h2hi, h2lo);

    // Layer 3: out = h2 @ W3^T + b3 (fp32)              [grid 8x16]
    gemm_fp16_kernel<0><<<dim3(OUT_DIM / 128, B_DIM / 128), 128, D_SMEM>>>(
        h2hi, h2lo, w3, b3, out, nullptr, nullptr, OUT_DIM, H_DIM);
}

// round 8
// speedup vs baseline: 2.1209x; 1.5549x over previous
#include <cuda_runtime.h>
#include <cuda_fp16.h>
#include <cstdint>

// Problem constants (fixed by dataset)
#define B_DIM   2048
#define IN_DIM  1024
#define H_DIM   2048
#define OUT_DIM 1024
#define BSB     32
#define RBX     64
#define NNZ     (64 * 32)

// ---------------------------------------------------------------------------
// Device globals (no allocation allowed). Plain fp16 everywhere.
// ---------------------------------------------------------------------------
__device__ __half g_x[(size_t)B_DIM * IN_DIM];
__device__ __half g_w1[(size_t)H_DIM * IN_DIM];
__device__ __half g_w3[(size_t)OUT_DIM * H_DIM];
__device__ __half g_vals[(size_t)NNZ * BSB * BSB];
__device__ __half g_h1[(size_t)B_DIM * H_DIM];
__device__ __half g_h2[(size_t)B_DIM * H_DIM];

// ---------------------------------------------------------------------------
// Helpers
// ---------------------------------------------------------------------------
__device__ __forceinline__ uint32_t smem_u32(const void* p) {
    uint32_t a;
    asm("{ .reg .u64 t; cvta.to.shared.u64 t, %1; cvt.u32.u64 %0, t; }"
        : "=r"(a) : "l"(p));
    return a;
}

__device__ __forceinline__ void cp16(uint32_t dst, const void* src) {
    asm volatile("cp.async.cg.shared.global [%0], [%1], 16;"
                 :: "r"(dst), "l"(src) : "memory");
}
#define CP_COMMIT() asm volatile("cp.async.commit_group;" ::: "memory")
#define CP_WAIT(N)  asm volatile("cp.async.wait_group %0;" :: "n"(N) : "memory")

__device__ __forceinline__ void ldsm_x4(uint32_t (&r)[4], uint32_t addr) {
    asm volatile("ldmatrix.sync.aligned.m8n8.x4.shared.b16 {%0,%1,%2,%3}, [%4];"
                 : "=r"(r[0]), "=r"(r[1]), "=r"(r[2]), "=r"(r[3]) : "r"(addr));
}

__device__ __forceinline__ void mma_fp16(float c[4], const uint32_t a[4],
                                         const uint32_t b[2]) {
    asm volatile(
        "mma.sync.aligned.m16n8k16.row.col.f32.f16.f16.f32 "
        "{%0,%1,%2,%3}, {%4,%5,%6,%7}, {%8,%9}, {%0,%1,%2,%3};"
        : "+f"(c[0]), "+f"(c[1]), "+f"(c[2]), "+f"(c[3])
        : "r"(a[0]), "r"(a[1]), "r"(a[2]), "r"(a[3]), "r"(b[0]), "r"(b[1]));
}

// ---------------------------------------------------------------------------
// Prep kernel: convert 4 fp32 arrays to plain fp16 (blockIdx.y selects array)
// ---------------------------------------------------------------------------
struct PrepArgs {
    const float4* src[4];
    uint2* dst[4];
};

__global__ __launch_bounds__(256) void prep_kernel(PrepArgs args, int n4)
{
    const int a = blockIdx.y;
    const int i = blockIdx.x * 256 + threadIdx.x;
    if (i >= n4) return;
    float4 v = args.src[a][i];
    __half2 h0 = __floats2half2_rn(v.x, v.y);
    __half2 h1 = __floats2half2_rn(v.z, v.w);
    uint2 u; u.x = *(uint32_t*)&h0; u.y = *(uint32_t*)&h1;
    args.dst[a][i] = u;
}

// ---------------------------------------------------------------------------
// Dense GEMM (NT): C = act(A @ B^T + bias). Plain fp16 operands, fp32 accum.
// CTA 128x128, 4 warps, warp tile 64x64, K-chunk 32, 2-stage cp.async.
// smem 40KB/CTA.
// MODE 0: fp32 out + bias.  MODE 1: relu, write fp16.
// ---------------------------------------------------------------------------
#define ROWB   80                    // 64B data + 16B pad
#define D_AT   (128 * ROWB)          // 10240 B per matrix tile
#define DSTG   (2 * D_AT)            // A, B -> 20480 B per stage
#define D_SMEM (2 * DSTG)            // 40960 B

template <int MODE>
__global__ __launch_bounds__(128, 2) void gemm_fp16_kernel(
    const __half* __restrict__ A, const __half* __restrict__ Bm,
    const float* __restrict__ bias, float* __restrict__ Cf,
    __half* __restrict__ Ch, int N, int K)
{
    extern __shared__ char sm[];
    const uint32_t sb = smem_u32(sm);
    const int tid  = threadIdx.x;
    const int lane = tid & 31;
    const int wid  = tid >> 5;
    const int brow = blockIdx.y * 128;
    const int bcol = blockIdx.x * 128;
    const int wm = (wid >> 1) * 64;
    const int wn = (wid & 1) * 64;
    const int chunks = K / 32;

    float acc[4][8][4];
#pragma unroll
    for (int i = 0; i < 4; i++)
#pragma unroll
        for (int j = 0; j < 8; j++)
#pragma unroll
            for (int r = 0; r < 4; r++) acc[i][j][r] = 0.0f;

    // cp.async: each matrix tile is 128 rows x 64B = 512 segs of 16B.
    auto issue = [&](int ki) {
        const int k0 = ki * 32;
        const uint32_t bufo = sb + (uint32_t)(ki & 1) * DSTG;
#pragma unroll
        for (int t = 0; t < 4; t++) {
            const int seg = tid + t * 128;
            const int row = seg >> 2, s = seg & 3;
            const uint32_t d = bufo + row * ROWB + s * 16;
            cp16(d,        A  + (size_t)(brow + row) * K + k0 + s * 8);
            cp16(d + D_AT, Bm + (size_t)(bcol + row) * K + k0 + s * 8);
        }
    };

    issue(0);
    CP_COMMIT();

    const uint32_t aoff = (wm + (lane & 15)) * ROWB + ((lane >> 4) & 1) * 16;
    const uint32_t boff = (wn + ((lane >> 4) & 1) * 8 + (lane & 7)) * ROWB +
                          ((lane >> 3) & 1) * 16;

    for (int kc = 0; kc < chunks; kc++) {
        if (kc + 1 < chunks) { issue(kc + 1); CP_COMMIT(); CP_WAIT(1); }
        else                 { CP_WAIT(0); }
        __syncthreads();

        const uint32_t base = sb + (uint32_t)(kc & 1) * DSTG;
#pragma unroll
        for (int ks = 0; ks < 2; ks++) {
            uint32_t bq[4][4];
#pragma unroll
            for (int jp = 0; jp < 4; jp++)
                ldsm_x4(bq[jp], base + D_AT + boff + jp * (16 * ROWB) + ks * 32);
            uint32_t af[4][4];
#pragma unroll
            for (int i = 0; i < 4; i++)
                ldsm_x4(af[i], base + aoff + i * (16 * ROWB) + ks * 32);
#pragma unroll
            for (int i = 0; i < 4; i++)
#pragma unroll
                for (int j = 0; j < 8; j++)
                    mma_fp16(acc[i][j], af[i], &bq[j >> 1][(j & 1) * 2]);
        }
        __syncthreads();
    }

    // epilogue
#pragma unroll
    for (int i = 0; i < 4; i++) {
        const int r0 = brow + wm + i * 16 + (lane >> 2);
#pragma unroll
        for (int j = 0; j < 8; j++) {
            const int c0 = bcol + wn + j * 8 + 2 * (lane & 3);
            const float bx = __ldg(&bias[c0]), by = __ldg(&bias[c0 + 1]);
            float v00 = acc[i][j][0] + bx, v01 = acc[i][j][1] + by;
            float v10 = acc[i][j][2] + bx, v11 = acc[i][j][3] + by;
            if (MODE == 0) {
                *(float2*)(Cf + (size_t)r0 * N + c0)       = make_float2(v00, v01);
                *(float2*)(Cf + (size_t)(r0 + 8) * N + c0) = make_float2(v10, v11);
            } else {
                v00 = fmaxf(v00, 0.f); v01 = fmaxf(v01, 0.f);
                v10 = fmaxf(v10, 0.f); v11 = fmaxf(v11, 0.f);
                *(__half2*)(Ch + (size_t)r0 * N + c0)       = __floats2half2_rn(v00, v01);
                *(__half2*)(Ch + (size_t)(r0 + 8) * N + c0) = __floats2half2_rn(v10, v11);
            }
        }
    }
}

// ---------------------------------------------------------------------------
// BSR layer: per (batch-tile 256, row-block rb):
//   h2[., rb*32:+32] = relu( sum_p h1[., col_p*32:+32] @ vals[p]^T + b2 )
// Plain fp16. 8 warps (32x32 warp tiles), 2-stage cp.async. smem 45KB.
// ---------------------------------------------------------------------------
#define S_AT   (256 * ROWB)                 // 20480 B (A tile)
#define S_BT   (32 * ROWB)                  // 2560 B  (B tile)
#define SSTG   (S_AT + S_BT)                // 23040 B per stage
#define S_SMEM (2 * SSTG)                   // 46080 B

__global__ __launch_bounds__(256, 2) void bsr_fp16_kernel(
    const __half* __restrict__ h1, const int* __restrict__ crow,
    const int* __restrict__ cols, const __half* __restrict__ vals,
    const float* __restrict__ bias, __half* __restrict__ h2)
{
    extern __shared__ char sm[];
    const uint32_t sb = smem_u32(sm);
    const int tid  = threadIdx.x;
    const int lane = tid & 31;
    const int wid  = tid >> 5;
    const int b0 = blockIdx.x * 256;
    const int rb = blockIdx.y;
    const int wm = wid * 32;

    float acc[2][4][4];
#pragma unroll
    for (int i = 0; i < 2; i++)
#pragma unroll
        for (int j = 0; j < 4; j++)
#pragma unroll
            for (int r = 0; r < 4; r++) acc[i][j][r] = 0.0f;

    const int s0 = __ldg(&crow[rb]);
    const int chunks = __ldg(&crow[rb + 1]) - s0;

    auto issue = [&](int ki) {
        const int p = s0 + ki;
        const int cb = __ldg(&cols[p]);
        const uint32_t bufo = sb + (uint32_t)(ki & 1) * SSTG;
        // A: 256 rows x 4 segs = 1024 segs
#pragma unroll
        for (int t = 0; t < 4; t++) {
            const int seg = tid + t * 256;
            const int row = seg >> 2, s = seg & 3;
            cp16(bufo + row * ROWB + s * 16,
                 h1 + (size_t)(b0 + row) * H_DIM + cb * 32 + s * 8);
        }
        // B: 32 rows x 4 segs = 128 segs
        if (tid < 128) {
            const int row = tid >> 2, s = tid & 3;
            cp16(bufo + S_AT + row * ROWB + s * 16,
                 vals + (size_t)p * (BSB * BSB) + row * BSB + s * 8);
        }
    };

    issue(0);
    CP_COMMIT();

    const uint32_t aoff = (wm + (lane & 15)) * ROWB + ((lane >> 4) & 1) * 16;
    const uint32_t boff = (((lane >> 4) & 1) * 8 + (lane & 7)) * ROWB +
                          ((lane >> 3) & 1) * 16;

    for (int kc = 0; kc < chunks; kc++) {
        if (kc + 1 < chunks) { issue(kc + 1); CP_COMMIT(); CP_WAIT(1); }
        else                 { CP_WAIT(0); }
        __syncthreads();

        const uint32_t base = sb + (uint32_t)(kc & 1) * SSTG;
#pragma unroll
        for (int ks = 0; ks < 2; ks++) {
            uint32_t bq[2][4];
#pragma unroll
            for (int jp = 0; jp < 2; jp++)
                ldsm_x4(bq[jp], base + S_AT + boff + jp * (16 * ROWB) + ks * 32);
            uint32_t af[2][4];
#pragma unroll
            for (int i = 0; i < 2; i++)
                ldsm_x4(af[i], base + aoff + i * (16 * ROWB) + ks * 32);
#pragma unroll
            for (int i = 0; i < 2; i++)
#pragma unroll
                for (int j = 0; j < 4; j++)
                    mma_fp16(acc[i][j], af[i], &bq[j >> 1][(j & 1) * 2]);
        }
        __syncthreads();
    }

    // epilogue: bias + relu -> fp16
#pragma unroll
    for (int i = 0; i < 2; i++) {
        const int r0 = b0 + wm + i * 16 + (lane >> 2);
#pragma unroll
        for (int j = 0; j < 4; j++) {
            const int c0 = rb * 32 + j * 8 + 2 * (lane & 3);
            const float bx = __ldg(&bias[c0]), by = __ldg(&bias[c0 + 1]);
            float v00 = fmaxf(acc[i][j][0] + bx, 0.f);
            float v01 = fmaxf(acc[i][j][1] + by, 0.f);
            float v10 = fmaxf(acc[i][j][2] + bx, 0.f);
            float v11 = fmaxf(acc[i][j][3] + by, 0.f);
            *(__half2*)(h2 + (size_t)r0 * H_DIM + c0)       = __floats2half2_rn(v00, v01);
            *(__half2*)(h2 + (size_t)(r0 + 8) * H_DIM + c0) = __floats2half2_rn(v10, v11);
        }
    }
}

// ---------------------------------------------------------------------------
// Launcher
// ---------------------------------------------------------------------------
extern "C" void kernel_launch(void* const* d_in, const int* in_sizes, int n_in,
                              void* d_out, int out_size)
{
    const float* x    = (const float*)d_in[0];
    const float* W1   = (const float*)d_in[1];
    const float* b1   = (const float*)d_in[2];
    const int*   crow = (const int*)d_in[3];
    const int*   cols = (const int*)d_in[4];
    const float* vals = (const float*)d_in[5];
    const float* b2   = (const float*)d_in[6];
    const float* W3   = (const float*)d_in[7];
    const float* b3   = (const float*)d_in[8];
    float* out = (float*)d_out;

    __half *xh, *w1, *w3, *vf, *h1, *h2;
    cudaGetSymbolAddress((void**)&xh, g_x);
    cudaGetSymbolAddress((void**)&w1, g_w1);
    cudaGetSymbolAddress((void**)&w3, g_w3);
    cudaGetSymbolAddress((void**)&vf, g_vals);
    cudaGetSymbolAddress((void**)&h1, g_h1);
    cudaGetSymbolAddress((void**)&h2, g_h2);

    cudaFuncSetAttribute(gemm_fp16_kernel<0>,
                         cudaFuncAttributeMaxDynamicSharedMemorySize, D_SMEM);
    cudaFuncSetAttribute(gemm_fp16_kernel<1>,
                         cudaFuncAttributeMaxDynamicSharedMemorySize, D_SMEM);
    cudaFuncSetAttribute(bsr_fp16_kernel,
                         cudaFuncAttributeMaxDynamicSharedMemorySize, S_SMEM);

    // Prep: convert x, W1, W3, vals to fp16 (each 2M elements = 512K float4)
    const int n4 = (B_DIM * IN_DIM) / 4;
    PrepArgs pa;
    pa.src[0] = (const float4*)x;    pa.dst[0] = (uint2*)xh;
    pa.src[1] = (const float4*)W1;   pa.dst[1] = (uint2*)w1;
    pa.src[2] = (const float4*)W3;   pa.dst[2] = (uint2*)w3;
    pa.src[3] = (const float4*)vals; pa.dst[3] = (uint2*)vf;
    prep_kernel<<<dim3(n4 / 256, 4), 256>>>(pa, n4);

    // Layer 1: h1 = relu(x @ W1^T + b1) -> fp16   [grid 16x16 = 256]
    gemm_fp16_kernel<1><<<dim3(H_DIM / 128, B_DIM / 128), 128, D_SMEM>>>(
        xh, w1, b1, nullptr, h1, H_DIM, IN_DIM);

    // Layer 2: h2 = relu(BSR(h1) + b2) -> fp16    [grid 8x64 = 512]
    bsr_fp16_kernel<<<dim3(B_DIM / 256, RBX), 256, S_SMEM>>>(
        h1, crow, cols, vf, b2, h2);

    // Layer 3: out = h2 @ W3^T + b3 (fp32)        [grid 8x16 = 128]
    gemm_fp16_kernel<0><<<dim3(OUT_DIM / 128, B_DIM / 128), 128, D_SMEM>>>(
        h2, w3, b3, out, nullptr, OUT_DIM, H_DIM);
}